// round 3
// baseline (speedup 1.0000x reference)
#include <cuda_runtime.h>
#include <math_constants.h>

#define VOCAB   50257
#define NBEAM   8
#define TOPK    8
#define HIST    128
#define LCNT    32
#define REST4   262144          /* KV2*HEADS*SEQ*HDIM/4 = 2*8*1024*64/4 */
#define KV_TOTAL 268435456LL    /* L*BEAM*KV2*HEADS*SEQ*HDIM */

__device__ float g_topprob[NBEAM * TOPK];
__device__ int   g_topidx[NBEAM * TOPK];
__device__ int   g_bi[NBEAM];

// ---------------------------------------------------------------------------
// Kernel 1: per beam-row (8 blocks), compute logsumexp and top-8 (value,index)
// ---------------------------------------------------------------------------
__global__ void k_rowtop(const float* __restrict__ logits) {
    const int b   = blockIdx.x;
    const int tid = threadIdx.x;
    const float* __restrict__ row = logits + (long long)b * VOCAB;

    __shared__ float sval[1024];
    __shared__ int   sidx[1024];
    __shared__ int   sel[TOPK];
    __shared__ float s_lse;

    // --- row max ---
    float m = -CUDART_INF_F;
    for (int i = tid; i < VOCAB; i += 1024) m = fmaxf(m, row[i]);
    sval[tid] = m; __syncthreads();
    for (int s = 512; s > 0; s >>= 1) {
        if (tid < s) sval[tid] = fmaxf(sval[tid], sval[tid + s]);
        __syncthreads();
    }
    const float rowmax = sval[0];
    __syncthreads();

    // --- sum exp(x - max) ---
    float acc = 0.f;
    for (int i = tid; i < VOCAB; i += 1024) acc += __expf(row[i] - rowmax);
    sval[tid] = acc; __syncthreads();
    for (int s = 512; s > 0; s >>= 1) {
        if (tid < s) sval[tid] += sval[tid + s];
        __syncthreads();
    }
    if (tid == 0) s_lse = rowmax + logf(sval[0]);
    __syncthreads();
    const float lse = s_lse;

    // --- top-8 by 8 masked argmax passes (row is L2-resident after pass 1) ---
    for (int k = 0; k < TOPK; k++) {
        int selreg[TOPK];
        #pragma unroll
        for (int j = 0; j < TOPK; j++) selreg[j] = (j < k) ? sel[j] : -1;

        float bv = -CUDART_INF_F; int bidx = 0x7fffffff;
        for (int i = tid; i < VOCAB; i += 1024) {
            bool skip = false;
            #pragma unroll
            for (int j = 0; j < TOPK; j++) skip |= (i == selreg[j]);
            float v = row[i];
            if (!skip && v > bv) { bv = v; bidx = i; }   // strict > keeps lowest index on ties
        }
        sval[tid] = bv; sidx[tid] = bidx; __syncthreads();
        for (int s = 512; s > 0; s >>= 1) {
            if (tid < s) {
                float vr = sval[tid + s]; int ir = sidx[tid + s];
                if (vr > sval[tid] || (vr == sval[tid] && ir < sidx[tid])) {
                    sval[tid] = vr; sidx[tid] = ir;
                }
            }
            __syncthreads();
        }
        if (tid == 0) {
            sel[k]                  = sidx[0];
            g_topprob[b * TOPK + k] = sval[0] - lse;
            g_topidx[b * TOPK + k]  = sidx[0];
        }
        __syncthreads();
    }
}

// ---------------------------------------------------------------------------
// Kernel 2: combine 64 candidates -> top-8 beams; write all small outputs
// ---------------------------------------------------------------------------
__global__ void k_combine(const float* __restrict__ prev,
                          const int* __restrict__ save_id,
                          float* __restrict__ out) {
    __shared__ int   s_bi[NBEAM];
    __shared__ int   s_tbi[NBEAM];
    __shared__ float s_prob[NBEAM];

    if (threadIdx.x == 0) {
        float cur[NBEAM * TOPK];
        bool  used[NBEAM * TOPK];
        #pragma unroll
        for (int j = 0; j < NBEAM * TOPK; j++) {
            cur[j]  = g_topprob[j] + prev[j >> 3];
            used[j] = false;
        }
        for (int k = 0; k < NBEAM; k++) {
            float bv = -CUDART_INF_F; int bj = 0;
            for (int j = 0; j < NBEAM * TOPK; j++)
                if (!used[j] && cur[j] > bv) { bv = cur[j]; bj = j; }
            used[bj]  = true;
            s_bi[k]   = bj >> 3;          // flat // top_k
            s_tbi[k]  = g_topidx[bj];
            s_prob[k] = bv;
            g_bi[k]   = bj >> 3;
        }
    }
    __syncthreads();

    float* o = out + KV_TOTAL;
    // new_save_id: (8, 129) = gathered save_id rows + appended token index
    for (int t = threadIdx.x; t < NBEAM * (HIST + 1); t += blockDim.x) {
        int ob = t / (HIST + 1), h = t % (HIST + 1);
        int v  = (h < HIST) ? save_id[s_bi[ob] * HIST + h] : s_tbi[ob];
        o[t]   = (float)v;
    }
    if (threadIdx.x < NBEAM) {
        o[NBEAM * (HIST + 1) + threadIdx.x]         = s_prob[threadIdx.x];        // top_beam_prob
        o[NBEAM * (HIST + 1) + NBEAM + threadIdx.x] = (float)s_tbi[threadIdx.x];  // tbi
    }
    if (threadIdx.x == 0)
        o[NBEAM * (HIST + 1) + 2 * NBEAM] = (float)s_tbi[0];                      // max_logits_idx
}

// ---------------------------------------------------------------------------
// Kernel 3: KV gather — the 1 GiB stream. Thread owns one (l, r) float4 slot,
// writes all 8 destination beams; duplicate source beams hit L1.
// ---------------------------------------------------------------------------
__global__ void __launch_bounds__(256) k_gather(const float4* __restrict__ kv,
                                                float4* __restrict__ out) {
    const long long t = (long long)blockIdx.x * blockDim.x + threadIdx.x; // [0, 32*REST4)
    const int l = (int)(t >> 18);            // / REST4
    const int r = (int)(t & (REST4 - 1));
    const long long base = (((long long)l * NBEAM) << 18) + r;

    int bi[NBEAM];
    #pragma unroll
    for (int ob = 0; ob < NBEAM; ob++) bi[ob] = g_bi[ob];

    float4 v[NBEAM];
    #pragma unroll
    for (int ob = 0; ob < NBEAM; ob++)
        v[ob] = __ldg(&kv[base + ((long long)bi[ob] << 18)]);
    #pragma unroll
    for (int ob = 0; ob < NBEAM; ob++)
        out[base + ((long long)ob << 18)] = v[ob];
}

// ---------------------------------------------------------------------------
extern "C" void kernel_launch(void* const* d_in, const int* in_sizes, int n_in,
                              void* d_out, int out_size) {
    const float* kv      = (const float*)d_in[0];
    const float* logits  = (const float*)d_in[1];
    const int*   save_id = (const int*)d_in[2];
    const float* prev    = (const float*)d_in[3];
    float*       out     = (float*)d_out;

    k_rowtop<<<NBEAM, 1024>>>(logits);
    k_combine<<<1, 256>>>(prev, save_id, out);
    // 32 * 262144 float4 slots / 256 threads = 32768 blocks (exact, no tail)
    k_gather<<<32768, 256>>>((const float4*)kv, (float4*)out);
}

// round 4
// speedup vs baseline: 1.1544x; 1.1544x over previous
#include <cuda_runtime.h>
#include <math_constants.h>

#define VOCAB   50257
#define NBEAM   8
#define TOPK    8
#define HIST    128
#define PARTS   16
#define CHUNK   3142            /* ceil(50257/16) */
#define TPB_A   256
#define REST4   262144          /* KV2*HEADS*SEQ*HDIM/4 */
#define KV_TOTAL 268435456LL    /* L*BEAM*KV2*HEADS*SEQ*HDIM */

__device__ float g_pm[NBEAM * PARTS];          // partial streaming-lse max
__device__ float g_ps[NBEAM * PARTS];          // partial sum exp(x - m)
__device__ float g_pv[NBEAM * PARTS * TOPK];   // per-part top-8 values
__device__ int   g_pi[NBEAM * PARTS * TOPK];   // per-part top-8 global indices
__device__ int   g_bi[NBEAM];

// ---------------------------------------------------------------------------
// Kernel 1: per (part, row) block. Stage chunk in smem, partial lse + top-8.
// ---------------------------------------------------------------------------
__global__ void __launch_bounds__(TPB_A) k_rowtop_part(const float* __restrict__ logits) {
    const int part = blockIdx.x, b = blockIdx.y;
    const int tid = threadIdx.x, lane = tid & 31, wid = tid >> 5;

    __shared__ float chunk[CHUNK];
    __shared__ float swv[8];  __shared__ int swi[8];
    __shared__ float swm[8];  __shared__ float sws[8];
    __shared__ int   sel[TOPK];

    const int base = part * CHUNK;
    const float* __restrict__ row = logits + (long long)b * VOCAB;

    // --- load chunk + per-thread streaming logsumexp ---
    float m = -CUDART_INF_F, s = 0.f;
    for (int i = tid; i < CHUNK; i += TPB_A) {
        int g = base + i;
        float v = (g < VOCAB) ? __ldg(row + g) : -CUDART_INF_F;
        chunk[i] = v;
        if (v > m)                     { s = s * __expf(m - v) + 1.f; m = v; }
        else if (v > -CUDART_INF_F)    { s += __expf(v - m); }
    }
    // warp-level lse merge
    for (int off = 16; off; off >>= 1) {
        float om = __shfl_down_sync(0xffffffffu, m, off);
        float os = __shfl_down_sync(0xffffffffu, s, off);
        if (om > m)                    { s = s * __expf(m - om) + os; m = om; }
        else if (om > -CUDART_INF_F)   { s += os * __expf(om - m); }
    }
    if (lane == 0) { swm[wid] = m; sws[wid] = s; }
    __syncthreads();   // chunk + swm/sws visible
    if (wid == 0) {
        m = (lane < 8) ? swm[lane] : -CUDART_INF_F;
        s = (lane < 8) ? sws[lane] : 0.f;
        for (int off = 4; off; off >>= 1) {
            float om = __shfl_down_sync(0xffffffffu, m, off);
            float os = __shfl_down_sync(0xffffffffu, s, off);
            if (om > m)                  { s = s * __expf(m - om) + os; m = om; }
            else if (om > -CUDART_INF_F) { s += os * __expf(om - m); }
        }
        if (lane == 0) { g_pm[b * PARTS + part] = m; g_ps[b * PARTS + part] = s; }
    }

    // --- top-8 via 8 masked argmax passes over the smem chunk ---
    for (int k = 0; k < TOPK; k++) {
        int selreg[TOPK];
        #pragma unroll
        for (int j = 0; j < TOPK; j++) selreg[j] = (j < k) ? sel[j] : -1;

        float bv = -CUDART_INF_F; int bidx = 0x7fffffff;
        for (int i = tid; i < CHUNK; i += TPB_A) {
            float v = chunk[i];
            bool skip = false;
            #pragma unroll
            for (int j = 0; j < TOPK; j++) skip |= (i == selreg[j]);
            if (!skip && v > bv) { bv = v; bidx = i; }  // ascending scan keeps lowest idx
        }
        for (int off = 16; off; off >>= 1) {
            float ov = __shfl_down_sync(0xffffffffu, bv, off);
            int   oi = __shfl_down_sync(0xffffffffu, bidx, off);
            if (ov > bv || (ov == bv && oi < bidx)) { bv = ov; bidx = oi; }
        }
        if (lane == 0) { swv[wid] = bv; swi[wid] = bidx; }
        __syncthreads();
        if (tid == 0) {
            #pragma unroll
            for (int w = 1; w < 8; w++)
                if (swv[w] > bv || (swv[w] == bv && swi[w] < bidx)) { bv = swv[w]; bidx = swi[w]; }
            sel[k] = bidx;
            g_pv[(b * PARTS + part) * TOPK + k] = bv;
            g_pi[(b * PARTS + part) * TOPK + k] = base + bidx;
        }
        __syncthreads();
    }
}

// ---------------------------------------------------------------------------
// Kernel 2: merge partials (warp per row), final 64-way combine, small outputs
// ---------------------------------------------------------------------------
__global__ void __launch_bounds__(256) k_combine(const float* __restrict__ prev,
                                                 const int* __restrict__ save_id,
                                                 float* __restrict__ out) {
    const int tid = threadIdx.x, lane = tid & 31, w = tid >> 5;  // w = beam row

    __shared__ float sh_prob[NBEAM * TOPK];
    __shared__ int   sh_idx[NBEAM * TOPK];
    __shared__ int   s_bi[NBEAM], s_tbi[NBEAM];
    __shared__ float s_sel[NBEAM];

    // --- row lse from 16 partials ---
    float m = (lane < PARTS) ? g_pm[w * PARTS + lane] : -CUDART_INF_F;
    float s = (lane < PARTS) ? g_ps[w * PARTS + lane] : 0.f;
    for (int off = 16; off; off >>= 1) {
        float om = __shfl_down_sync(0xffffffffu, m, off);
        float os = __shfl_down_sync(0xffffffffu, s, off);
        if (om > m)                  { s = s * __expf(m - om) + os; m = om; }
        else if (om > -CUDART_INF_F) { s += os * __expf(om - m); }
    }
    float lse = __shfl_sync(0xffffffffu, m + logf(s), 0);

    // --- merge 128 candidates -> top-8 (warp-parallel, 4 per lane) ---
    float cv[4]; int ci[4]; bool used[4];
    #pragma unroll
    for (int j = 0; j < 4; j++) {
        int c = w * PARTS * TOPK + j * 32 + lane;
        cv[j] = g_pv[c]; ci[j] = g_pi[c]; used[j] = false;
    }
    for (int k = 0; k < TOPK; k++) {
        float bv = -CUDART_INF_F; int bidx = 0x7fffffff;
        #pragma unroll
        for (int j = 0; j < 4; j++)
            if (!used[j] && (cv[j] > bv || (cv[j] == bv && ci[j] < bidx))) { bv = cv[j]; bidx = ci[j]; }
        for (int off = 16; off; off >>= 1) {
            float ov = __shfl_down_sync(0xffffffffu, bv, off);
            int   oi = __shfl_down_sync(0xffffffffu, bidx, off);
            if (ov > bv || (ov == bv && oi < bidx)) { bv = ov; bidx = oi; }
        }
        bv   = __shfl_sync(0xffffffffu, bv, 0);
        bidx = __shfl_sync(0xffffffffu, bidx, 0);
        #pragma unroll
        for (int j = 0; j < 4; j++)
            if (cv[j] == bv && ci[j] == bidx) used[j] = true;   // token idx unique per row
        if (lane == 0) { sh_prob[w * TOPK + k] = bv - lse; sh_idx[w * TOPK + k] = bidx; }
    }
    __syncthreads();

    // --- final top-8 over 64 candidates (serial, 64 entries) ---
    if (tid == 0) {
        float cur[NBEAM * TOPK]; bool usedf[NBEAM * TOPK];
        #pragma unroll
        for (int j = 0; j < NBEAM * TOPK; j++) { cur[j] = sh_prob[j] + prev[j >> 3]; usedf[j] = false; }
        for (int k = 0; k < NBEAM; k++) {
            float bv = -CUDART_INF_F; int bj = 0;
            for (int j = 0; j < NBEAM * TOPK; j++)
                if (!usedf[j] && cur[j] > bv) { bv = cur[j]; bj = j; }
            usedf[bj] = true;
            s_bi[k]  = bj >> 3;
            s_tbi[k] = sh_idx[bj];
            s_sel[k] = bv;
            g_bi[k]  = bj >> 3;
        }
    }
    __syncthreads();

    float* o = out + KV_TOTAL;
    for (int t = tid; t < NBEAM * (HIST + 1); t += blockDim.x) {
        int ob = t / (HIST + 1), h = t % (HIST + 1);
        int v  = (h < HIST) ? save_id[s_bi[ob] * HIST + h] : s_tbi[ob];
        o[t]   = (float)v;
    }
    if (tid < NBEAM) {
        o[NBEAM * (HIST + 1) + tid]         = s_sel[tid];          // top_beam_prob
        o[NBEAM * (HIST + 1) + NBEAM + tid] = (float)s_tbi[tid];   // tbi
    }
    if (tid == 0)
        o[NBEAM * (HIST + 1) + 2 * NBEAM] = (float)s_tbi[0];       // max_logits_idx
}

// ---------------------------------------------------------------------------
// Kernel 3: KV gather — 1 GiB stream (unchanged, near roofline)
// ---------------------------------------------------------------------------
__global__ void __launch_bounds__(256) k_gather(const float4* __restrict__ kv,
                                                float4* __restrict__ out) {
    const long long t = (long long)blockIdx.x * blockDim.x + threadIdx.x;
    const int l = (int)(t >> 18);
    const int r = (int)(t & (REST4 - 1));
    const long long base = (((long long)l * NBEAM) << 18) + r;

    int bi[NBEAM];
    #pragma unroll
    for (int ob = 0; ob < NBEAM; ob++) bi[ob] = g_bi[ob];

    float4 v[NBEAM];
    #pragma unroll
    for (int ob = 0; ob < NBEAM; ob++)
        v[ob] = __ldg(&kv[base + ((long long)bi[ob] << 18)]);
    #pragma unroll
    for (int ob = 0; ob < NBEAM; ob++)
        out[base + ((long long)ob << 18)] = v[ob];
}

// ---------------------------------------------------------------------------
extern "C" void kernel_launch(void* const* d_in, const int* in_sizes, int n_in,
                              void* d_out, int out_size) {
    const float* kv      = (const float*)d_in[0];
    const float* logits  = (const float*)d_in[1];
    const int*   save_id = (const int*)d_in[2];
    const float* prev    = (const float*)d_in[3];
    float*       out     = (float*)d_out;

    dim3 gA(PARTS, NBEAM);
    k_rowtop_part<<<gA, TPB_A>>>(logits);
    k_combine<<<1, 256>>>(prev, save_id, out);
    k_gather<<<32768, 256>>>((const float4*)kv, (float4*)out);
}